// round 6
// baseline (speedup 1.0000x reference)
#include <cuda_runtime.h>
#include <math.h>

#define LL 2
#define TT 512
#define BB 64
#define HH 512
#define AT 200
#define EE 512
#define VV 10000
#define SS 128
#define LTD (LL*TT)   // 1024

// ------------------------- scratch (static device memory) -------------------------
__device__ float d_kproj[(size_t)LL*TT*BB*AT];     // 13.1M
__device__ float d_xemb [(size_t)SS*BB*EE];        // 4.2M
__device__ float d_giEmb[(size_t)SS*BB*3*HH];      // 12.6M
__device__ float d_hstates[(size_t)SS*BB*HH];      // 4.2M
__device__ float d_h0[2][BB*HH];
__device__ float d_h1[2][BB*HH];
__device__ float d_q[LL*BB*AT];
__device__ float d_scores[BB*LTD];
__device__ float d_ctx[BB*HH];
__device__ float d_gi0[BB*3*HH];
__device__ float d_gh0[BB*3*HH];
__device__ float d_gi1[BB*3*HH];
__device__ float d_gh1[BB*3*HH];

__device__ __forceinline__ float sigm(float x){ return 1.0f/(1.0f + __expf(-x)); }
__device__ __forceinline__ float tanh_fast(float x){
    float y; asm("tanh.approx.f32 %0, %1;" : "=f"(y) : "f"(x)); return y;
}

// ------------------------- init h from encoder_final_states -------------------------
__global__ void k_init(const float* __restrict__ efs){
    int i = blockIdx.x*blockDim.x + threadIdx.x;
    if (i < BB*HH){ d_h0[0][i] = efs[i]; d_h1[0][i] = efs[BB*HH + i]; }
}

// ------------------------- embedding + relu for all steps -------------------------
__global__ void k_embed(const int* __restrict__ tgt, const float* __restrict__ emb){
    int sb = blockIdx.x;           // s*BB + b
    int s = sb / BB, b = sb % BB;
    int tok = (s == 0) ? 0 : tgt[b*SS + (s-1)];
    const float4* src = reinterpret_cast<const float4*>(emb + (size_t)tok*EE);
    float4* dst = reinterpret_cast<float4*>(d_xemb + (size_t)sb*EE);
    float4 v = src[threadIdx.x];
    v.x = fmaxf(v.x, 0.f); v.y = fmaxf(v.y, 0.f); v.z = fmaxf(v.z, 0.f); v.w = fmaxf(v.w, 0.f);
    dst[threadIdx.x] = v;
}

// ------------------------- generic fp32 NT-GEMM: C[m,n] = sum_k A[m,k]*B[n,k] -------------------------
// BM=128, BN=64, BK=16, 256 threads, 8x4 per thread. M must be multiple of 128, K of 16.
template<bool PERM>
__global__ void __launch_bounds__(256) k_sgemm(
    const float* __restrict__ Ag, int lda, long long strideA,
    const float* __restrict__ Bg, int ldb, long long strideB,
    const float* __restrict__ bias, int strideBias,
    float* __restrict__ Cg, int ldc, long long strideC,
    int M, int N, int K)
{
    int z = blockIdx.z;
    const float* A  = Ag + (size_t)z*strideA;
    const float* Bw = Bg + (size_t)z*strideB;
    float* C = Cg + (size_t)z*strideC;
    const float* bi = bias ? (bias + (size_t)z*strideBias) : nullptr;

    __shared__ float As[16][132];
    __shared__ float Bs[16][68];

    int m0 = blockIdx.x*128, n0 = blockIdx.y*64;
    int tid = threadIdx.x;
    int ty = tid >> 4, tx = tid & 15;

    float acc[8][4];
    #pragma unroll
    for (int i=0;i<8;i++)
        #pragma unroll
        for (int j=0;j<4;j++) acc[i][j] = 0.f;

    for (int k0 = 0; k0 < K; k0 += 16){
        #pragma unroll
        for (int r=0;r<2;r++){
            int id = tid + r*256;
            int row = id >> 2, kc = (id & 3) << 2;
            float4 v = *reinterpret_cast<const float4*>(A + (size_t)(m0+row)*lda + k0 + kc);
            As[kc+0][row]=v.x; As[kc+1][row]=v.y; As[kc+2][row]=v.z; As[kc+3][row]=v.w;
        }
        {
            int row = tid >> 2, kc = (tid & 3) << 2;
            float4 v = make_float4(0.f,0.f,0.f,0.f);
            if (n0 + row < N)
                v = *reinterpret_cast<const float4*>(Bw + (size_t)(n0+row)*ldb + k0 + kc);
            Bs[kc+0][row]=v.x; Bs[kc+1][row]=v.y; Bs[kc+2][row]=v.z; Bs[kc+3][row]=v.w;
        }
        __syncthreads();
        #pragma unroll
        for (int kk=0; kk<16; kk++){
            float4 a0 = *reinterpret_cast<const float4*>(&As[kk][ty*8]);
            float4 a1 = *reinterpret_cast<const float4*>(&As[kk][ty*8+4]);
            float4 b4 = *reinterpret_cast<const float4*>(&Bs[kk][tx*4]);
            float a[8] = {a0.x,a0.y,a0.z,a0.w,a1.x,a1.y,a1.z,a1.w};
            float bb[4] = {b4.x,b4.y,b4.z,b4.w};
            #pragma unroll
            for (int i=0;i<8;i++)
                #pragma unroll
                for (int j=0;j<4;j++)
                    acc[i][j] = fmaf(a[i], bb[j], acc[i][j]);
        }
        __syncthreads();
    }

    #pragma unroll
    for (int i=0;i<8;i++){
        int m = m0 + ty*8 + i;
        #pragma unroll
        for (int j=0;j<4;j++){
            int n = n0 + tx*4 + j;
            if (n < N){
                float v = acc[i][j] + (bi ? bi[n] : 0.f);
                if (PERM){
                    // m = s*BB + b ; out layout (B, S, V)
                    int srow = m >> 6, brow = m & 63;
                    C[((size_t)brow*SS + srow)*VV + n] = v;
                } else {
                    C[(size_t)m*ldc + n] = v;
                }
            }
        }
    }
}

// ------------------------- q = Qw @ h + Qb  (warp per output) -------------------------
__global__ void k_q(const float* __restrict__ Qw, const float* __restrict__ Qb, int cur){
    int gw = (blockIdx.x*256 + threadIdx.x) >> 5;
    int lane = threadIdx.x & 31;
    int l = gw / (BB*AT);
    int rem = gw - l*BB*AT;
    int b = rem / AT;
    int a = rem - b*AT;
    const float4* hr = reinterpret_cast<const float4*>((l==0 ? d_h0[cur] : d_h1[cur]) + (size_t)b*HH);
    const float4* wr = reinterpret_cast<const float4*>(Qw + (size_t)(l*AT + a)*HH);
    float sum = 0.f;
    #pragma unroll
    for (int i=0;i<4;i++){
        float4 h4 = hr[lane + i*32];
        float4 w4 = wr[lane + i*32];
        sum += h4.x*w4.x + h4.y*w4.y + h4.z*w4.z + h4.w*w4.w;
    }
    #pragma unroll
    for (int off=16; off; off>>=1) sum += __shfl_xor_sync(0xffffffffu, sum, off);
    if (lane == 0) d_q[gw] = sum + Qb[l*AT + a];
}

// ------------------------- scores[l,t,b] = Vw . tanh(q + kproj) + Vb  (warp per (l,t,b)) ---------
__global__ void k_scores(const float* __restrict__ Vw, const float* __restrict__ Vb){
    int gw = (blockIdx.x*256 + threadIdx.x) >> 5;    // gw = (l*T+t)*B + b
    int lane = threadIdx.x & 31;
    int b  = gw & 63;
    int lt = gw >> 6;
    int l  = lt >> 9;
    const float4* kp = reinterpret_cast<const float4*>(d_kproj + (size_t)gw*AT);
    const float4* qr = reinterpret_cast<const float4*>(d_q + (size_t)(l*BB + b)*AT);
    const float4* vw = reinterpret_cast<const float4*>(Vw + l*AT);
    float sum = 0.f;
    {
        float4 k4 = kp[lane], q4 = qr[lane], v4 = vw[lane];
        sum += v4.x*tanh_fast(k4.x+q4.x) + v4.y*tanh_fast(k4.y+q4.y)
             + v4.z*tanh_fast(k4.z+q4.z) + v4.w*tanh_fast(k4.w+q4.w);
    }
    if (lane < 18){
        float4 k4 = kp[lane+32], q4 = qr[lane+32], v4 = vw[lane+32];
        sum += v4.x*tanh_fast(k4.x+q4.x) + v4.y*tanh_fast(k4.y+q4.y)
             + v4.z*tanh_fast(k4.z+q4.z) + v4.w*tanh_fast(k4.w+q4.w);
    }
    #pragma unroll
    for (int off=16; off; off>>=1) sum += __shfl_xor_sync(0xffffffffu, sum, off);
    if (lane == 0) d_scores[(size_t)b*LTD + lt] = sum + Vb[l];
}

// ------------------------- softmax over (l,t) + context  (block per (b, h-chunk)) -------------------
__global__ void k_softctx(const float* __restrict__ enc){
    __shared__ float w[LTD];
    __shared__ float red[128];
    int b = blockIdx.x, hc = blockIdx.y, tid = threadIdx.x;
    const float* sc = d_scores + (size_t)b*LTD;

    float loc[8]; float mx = -1e30f;
    #pragma unroll
    for (int i=0;i<8;i++){ loc[i] = sc[tid + i*128]; mx = fmaxf(mx, loc[i]); }
    red[tid] = mx; __syncthreads();
    for (int st=64; st>0; st>>=1){ if (tid<st) red[tid]=fmaxf(red[tid],red[tid+st]); __syncthreads(); }
    float m = red[0]; __syncthreads();
    float se = 0.f;
    #pragma unroll
    for (int i=0;i<8;i++){ float e = __expf(loc[i]-m); w[tid + i*128] = e; se += e; }
    red[tid] = se; __syncthreads();
    for (int st=64; st>0; st>>=1){ if (tid<st) red[tid]+=red[tid+st]; __syncthreads(); }
    float inv = 1.0f/red[0];

    int h = hc*128 + tid;
    const float* ep = enc + (size_t)b*HH + h;   // + lt * (BB*HH)
    float acc = 0.f;
    #pragma unroll 8
    for (int lt=0; lt<LTD; lt++) acc = fmaf(w[lt], ep[(size_t)lt*BB*HH], acc);
    d_ctx[(size_t)b*HH + h] = acc*inv;
}

// ------------------------- per-step GRU matmuls (gi & gh in one launch) -------------------------
// M=64, N=1536, K=512. BN=16, BK=16, 256 threads, 4 rows per thread.
__global__ void __launch_bounds__(256) k_grumm(
    int layer, int s, int cur,
    const float* __restrict__ Wih0, const float* __restrict__ Whh0, const float* __restrict__ bhh0,
    const float* __restrict__ Wih1, const float* __restrict__ bih1,
    const float* __restrict__ Whh1, const float* __restrict__ bhh1)
{
    const float* Aa; const float* Bw; int ldb;
    const float* add = nullptr; const float* bias = nullptr; float* C;
    if (layer == 0){
        if (blockIdx.y == 0){ Aa = d_ctx;        Bw = Wih0 + EE; ldb = EE + HH; add = d_giEmb + (size_t)s*BB*3*HH; C = d_gi0; }
        else                { Aa = d_h0[cur];    Bw = Whh0;      ldb = HH;      bias = bhh0;                        C = d_gh0; }
    } else {
        if (blockIdx.y == 0){ Aa = d_h0[cur^1];  Bw = Wih1;      ldb = HH;      bias = bih1;                        C = d_gi1; }
        else                { Aa = d_h1[cur];    Bw = Whh1;      ldb = HH;      bias = bhh1;                        C = d_gh1; }
    }
    __shared__ float As[16][68];
    __shared__ float Bs[16][20];
    int tid = threadIdx.x;
    int n0 = blockIdx.x*16;
    int ty = tid >> 4, tx = tid & 15;
    int tm0 = ty*4;
    int arow = tid >> 2, akc = (tid & 3) << 2;
    float acc0=0.f, acc1=0.f, acc2=0.f, acc3=0.f;

    for (int k0=0; k0<HH; k0+=16){
        float4 av = *reinterpret_cast<const float4*>(Aa + (size_t)arow*HH + k0 + akc);
        As[akc+0][arow]=av.x; As[akc+1][arow]=av.y; As[akc+2][arow]=av.z; As[akc+3][arow]=av.w;
        if (tid < 64){
            float4 bv = *reinterpret_cast<const float4*>(Bw + (size_t)(n0 + arow)*ldb + k0 + akc);
            Bs[akc+0][arow]=bv.x; Bs[akc+1][arow]=bv.y; Bs[akc+2][arow]=bv.z; Bs[akc+3][arow]=bv.w;
        }
        __syncthreads();
        #pragma unroll
        for (int kk=0; kk<16; kk++){
            float4 a = *reinterpret_cast<const float4*>(&As[kk][tm0]);
            float bv = Bs[kk][tx];
            acc0 = fmaf(a.x, bv, acc0);
            acc1 = fmaf(a.y, bv, acc1);
            acc2 = fmaf(a.z, bv, acc2);
            acc3 = fmaf(a.w, bv, acc3);
        }
        __syncthreads();
    }
    int n = n0 + tx;
    float base = bias ? bias[n] : 0.f;
    float r[4] = {acc0+base, acc1+base, acc2+base, acc3+base};
    #pragma unroll
    for (int i=0;i<4;i++){
        size_t off = (size_t)(tm0+i)*(3*HH) + n;
        float v = r[i];
        if (add) v += add[off];
        C[off] = v;
    }
}

// ------------------------- GRU gates -------------------------
__global__ void k_gates0(int cur){
    int idx = blockIdx.x*256 + threadIdx.x;       // BB*HH
    int b = idx >> 9, j = idx & 511;
    const float* gi = d_gi0 + (size_t)b*3*HH;
    const float* gh = d_gh0 + (size_t)b*3*HH;
    float r = sigm(gi[j] + gh[j]);
    float z = sigm(gi[j+HH] + gh[j+HH]);
    float n = tanhf(gi[j+2*HH] + r*gh[j+2*HH]);
    d_h0[cur^1][idx] = (1.0f - z)*n + z*d_h0[cur][idx];
}
__global__ void k_gates1(int cur, int s){
    int idx = blockIdx.x*256 + threadIdx.x;
    int b = idx >> 9, j = idx & 511;
    const float* gi = d_gi1 + (size_t)b*3*HH;
    const float* gh = d_gh1 + (size_t)b*3*HH;
    float r = sigm(gi[j] + gh[j]);
    float z = sigm(gi[j+HH] + gh[j+HH]);
    float n = tanhf(gi[j+2*HH] + r*gh[j+2*HH]);
    float hv = (1.0f - z)*n + z*d_h1[cur][idx];
    d_h1[cur^1][idx] = hv;
    d_hstates[(size_t)s*BB*HH + idx] = hv;
}

// ------------------------- launch -------------------------
extern "C" void kernel_launch(void* const* d_in, const int* in_sizes, int n_in,
                              void* d_out, int out_size){
    const float* enc = (const float*)d_in[0];
    const float* efs = (const float*)d_in[1];
    const int*   tgt = (const int*)  d_in[2];
    const float* Qw  = (const float*)d_in[3];
    const float* Qb  = (const float*)d_in[4];
    const float* Kw  = (const float*)d_in[5];
    const float* Kb  = (const float*)d_in[6];
    const float* Vw  = (const float*)d_in[7];
    const float* Vb  = (const float*)d_in[8];
    const float* emb = (const float*)d_in[9];
    const float* Wih0= (const float*)d_in[10];
    const float* Whh0= (const float*)d_in[11];
    const float* bih0= (const float*)d_in[12];
    const float* bhh0= (const float*)d_in[13];
    const float* Wih1= (const float*)d_in[14];
    const float* Whh1= (const float*)d_in[15];
    const float* bih1= (const float*)d_in[16];
    const float* bhh1= (const float*)d_in[17];
    const float* Pw  = (const float*)d_in[18];
    const float* Pb  = (const float*)d_in[19];
    float* out = (float*)d_out;

    float *p_xemb, *p_giEmb, *p_kproj, *p_hstates;
    cudaGetSymbolAddress((void**)&p_xemb,    d_xemb);
    cudaGetSymbolAddress((void**)&p_giEmb,   d_giEmb);
    cudaGetSymbolAddress((void**)&p_kproj,   d_kproj);
    cudaGetSymbolAddress((void**)&p_hstates, d_hstates);

    // one-time precomputation (still timed every replay, like the reference)
    k_init<<<(BB*HH + 255)/256, 256>>>(efs);
    k_embed<<<SS*BB, 128>>>(tgt, emb);
    {   // gi_emb[s,b,:] = relu(emb) @ Wih0[:, :EE]^T + bih0   (M=8192, N=1536, K=512)
        dim3 g(SS*BB/128, (3*HH)/64, 1);
        k_sgemm<false><<<g, 256>>>(p_xemb, EE, 0, Wih0, EE+HH, 0, bih0, 0,
                                   p_giEmb, 3*HH, 0, SS*BB, 3*HH, EE);
    }
    {   // kproj[l,t,b,:] = enc @ Kw[l]^T + Kb[l]   (batched over l)
        dim3 g(TT*BB/128, (AT+63)/64, LL);
        k_sgemm<false><<<g, 256>>>(enc, HH, (long long)TT*BB*HH,
                                   Kw, HH, (long long)AT*HH,
                                   Kb, AT,
                                   p_kproj, AT, (long long)TT*BB*AT,
                                   TT*BB, AT, HH);
    }

    // sequential decode loop
    for (int s = 0; s < SS; s++){
        int cur = s & 1;
        k_q<<<(LL*BB*AT)/8, 256>>>(Qw, Qb, cur);
        k_scores<<<(LL*TT*BB)/8, 256>>>(Vw, Vb);
        { dim3 gs(BB, HH/128); k_softctx<<<gs, 128>>>(enc); }
        { dim3 gm(3*HH/16, 2);
          k_grumm<<<gm, 256>>>(0, s, cur, Wih0, Whh0, bhh0, Wih1, bih1, Whh1, bhh1);
          k_gates0<<<BB*HH/256, 256>>>(cur);
          k_grumm<<<gm, 256>>>(1, s, cur, Wih0, Whh0, bhh0, Wih1, bih1, Whh1, bhh1);
          k_gates1<<<BB*HH/256, 256>>>(cur, s);
        }
    }

    {   // deferred output projection: logits = hstates @ Pw^T + Pb, permuted to (B,S,V)
        dim3 g(SS*BB/128, (VV+63)/64, 1);
        k_sgemm<true><<<g, 256>>>(p_hstates, HH, 0, Pw, HH, 0, Pb, 0,
                                  out, VV, 0, SS*BB, VV, HH);
    }
}

// round 7
// speedup vs baseline: 1.8462x; 1.8462x over previous
#include <cuda_runtime.h>
#include <cuda_bf16.h>
#include <math.h>

#define LL 2
#define TT 512
#define BB 64
#define HH 512
#define AT 200
#define EE 512
#define VV 10000
#define SS 128
#define LTD (LL*TT)   // 1024

// ------------------------- scratch (static device memory) -------------------------
__device__ float d_kproj[(size_t)LL*TT*BB*AT];            // fp32 GEMM out
__device__ __nv_bfloat16 d_kprojh[(size_t)LL*TT*BB*AT];   // bf16 copy (26 MB)
__device__ __nv_bfloat16 d_ench[(size_t)BB*LTD*HH];       // enc transposed (b,lt,h) bf16 (67 MB)
__device__ float d_xemb [(size_t)SS*BB*EE];
__device__ float d_giEmb[(size_t)SS*BB*3*HH];
__device__ float d_hstates[(size_t)SS*BB*HH];
__device__ float d_h0[2][BB*HH];
__device__ float d_h1[2][BB*HH];
__device__ float d_q[LL*BB*AT];
__device__ float d_scores[BB*LTD];
__device__ float d_ctxp[4*BB*HH];                         // 4 lt-split partial contexts
__device__ float d_gi0[BB*3*HH];
__device__ float d_gh0[BB*3*HH];
__device__ float d_gi1[BB*3*HH];
__device__ float d_gh1[BB*3*HH];

__device__ __forceinline__ float sigm(float x){ return 1.0f/(1.0f + __expf(-x)); }
__device__ __forceinline__ float tanh_fast(float x){
    float y; asm("tanh.approx.f32 %0, %1;" : "=f"(y) : "f"(x)); return y;
}

// ------------------------- init h from encoder_final_states -------------------------
__global__ void k_init(const float* __restrict__ efs){
    int i = blockIdx.x*blockDim.x + threadIdx.x;
    if (i < BB*HH){ d_h0[0][i] = efs[i]; d_h1[0][i] = efs[BB*HH + i]; }
}

// ------------------------- embedding + relu for all steps -------------------------
__global__ void k_embed(const int* __restrict__ tgt, const float* __restrict__ emb){
    int sb = blockIdx.x;           // s*BB + b
    int s = sb / BB, b = sb % BB;
    int tok = (s == 0) ? 0 : tgt[b*SS + (s-1)];
    const float4* src = reinterpret_cast<const float4*>(emb + (size_t)tok*EE);
    float4* dst = reinterpret_cast<float4*>(d_xemb + (size_t)sb*EE);
    float4 v = src[threadIdx.x];
    v.x = fmaxf(v.x, 0.f); v.y = fmaxf(v.y, 0.f); v.z = fmaxf(v.z, 0.f); v.w = fmaxf(v.w, 0.f);
    dst[threadIdx.x] = v;
}

// ------------------------- bf16 converts (once) -------------------------
__global__ void k_kproj2bf(){
    size_t n2 = (size_t)LL*TT*BB*AT/2;
    for (size_t i = blockIdx.x*(size_t)blockDim.x + threadIdx.x; i < n2; i += (size_t)gridDim.x*blockDim.x){
        float2 v = reinterpret_cast<const float2*>(d_kproj)[i];
        reinterpret_cast<__nv_bfloat162*>(d_kprojh)[i] = __floats2bfloat162_rn(v.x, v.y);
    }
}
__global__ void k_enc2bf(const float* __restrict__ enc){
    int lt = blockIdx.x;   // 1024
    int tid = threadIdx.x; // 256
    for (int b = 0; b < BB; b++){
        float2 v = *reinterpret_cast<const float2*>(enc + ((size_t)lt*BB + b)*HH + 2*tid);
        reinterpret_cast<__nv_bfloat162*>(d_ench + ((size_t)b*LTD + lt)*HH)[tid] =
            __floats2bfloat162_rn(v.x, v.y);
    }
}

// ------------------------- generic fp32 NT-GEMM: C[m,n] = sum_k A[m,k]*B[n,k] -------------------------
template<bool PERM>
__global__ void __launch_bounds__(256) k_sgemm(
    const float* __restrict__ Ag, int lda, long long strideA,
    const float* __restrict__ Bg, int ldb, long long strideB,
    const float* __restrict__ bias, int strideBias,
    float* __restrict__ Cg, int ldc, long long strideC,
    int M, int N, int K)
{
    int z = blockIdx.z;
    const float* A  = Ag + (size_t)z*strideA;
    const float* Bw = Bg + (size_t)z*strideB;
    float* C = Cg + (size_t)z*strideC;
    const float* bi = bias ? (bias + (size_t)z*strideBias) : nullptr;

    __shared__ float As[16][132];
    __shared__ float Bs[16][68];

    int m0 = blockIdx.x*128, n0 = blockIdx.y*64;
    int tid = threadIdx.x;
    int ty = tid >> 4, tx = tid & 15;

    float acc[8][4];
    #pragma unroll
    for (int i=0;i<8;i++)
        #pragma unroll
        for (int j=0;j<4;j++) acc[i][j] = 0.f;

    for (int k0 = 0; k0 < K; k0 += 16){
        #pragma unroll
        for (int r=0;r<2;r++){
            int id = tid + r*256;
            int row = id >> 2, kc = (id & 3) << 2;
            float4 v = *reinterpret_cast<const float4*>(A + (size_t)(m0+row)*lda + k0 + kc);
            As[kc+0][row]=v.x; As[kc+1][row]=v.y; As[kc+2][row]=v.z; As[kc+3][row]=v.w;
        }
        {
            int row = tid >> 2, kc = (tid & 3) << 2;
            float4 v = make_float4(0.f,0.f,0.f,0.f);
            if (n0 + row < N)
                v = *reinterpret_cast<const float4*>(Bw + (size_t)(n0+row)*ldb + k0 + kc);
            Bs[kc+0][row]=v.x; Bs[kc+1][row]=v.y; Bs[kc+2][row]=v.z; Bs[kc+3][row]=v.w;
        }
        __syncthreads();
        #pragma unroll
        for (int kk=0; kk<16; kk++){
            float4 a0 = *reinterpret_cast<const float4*>(&As[kk][ty*8]);
            float4 a1 = *reinterpret_cast<const float4*>(&As[kk][ty*8+4]);
            float4 b4 = *reinterpret_cast<const float4*>(&Bs[kk][tx*4]);
            float a[8] = {a0.x,a0.y,a0.z,a0.w,a1.x,a1.y,a1.z,a1.w};
            float bb[4] = {b4.x,b4.y,b4.z,b4.w};
            #pragma unroll
            for (int i=0;i<8;i++)
                #pragma unroll
                for (int j=0;j<4;j++)
                    acc[i][j] = fmaf(a[i], bb[j], acc[i][j]);
        }
        __syncthreads();
    }

    #pragma unroll
    for (int i=0;i<8;i++){
        int m = m0 + ty*8 + i;
        #pragma unroll
        for (int j=0;j<4;j++){
            int n = n0 + tx*4 + j;
            if (n < N){
                float v = acc[i][j] + (bi ? bi[n] : 0.f);
                if (PERM){
                    int srow = m >> 6, brow = m & 63;
                    C[((size_t)brow*SS + srow)*VV + n] = v;
                } else {
                    C[(size_t)m*ldc + n] = v;
                }
            }
        }
    }
}

// ------------------------- q = Qw @ h + Qb  (warp per output) -------------------------
__global__ void k_q(const float* __restrict__ Qw, const float* __restrict__ Qb, int cur){
    int gw = (blockIdx.x*256 + threadIdx.x) >> 5;
    int lane = threadIdx.x & 31;
    int l = gw / (BB*AT);
    int rem = gw - l*BB*AT;
    int b = rem / AT;
    int a = rem - b*AT;
    const float4* hr = reinterpret_cast<const float4*>((l==0 ? d_h0[cur] : d_h1[cur]) + (size_t)b*HH);
    const float4* wr = reinterpret_cast<const float4*>(Qw + (size_t)(l*AT + a)*HH);
    float sum = 0.f;
    #pragma unroll
    for (int i=0;i<4;i++){
        float4 h4 = hr[lane + i*32];
        float4 w4 = wr[lane + i*32];
        sum += h4.x*w4.x + h4.y*w4.y + h4.z*w4.z + h4.w*w4.w;
    }
    #pragma unroll
    for (int off=16; off; off>>=1) sum += __shfl_xor_sync(0xffffffffu, sum, off);
    if (lane == 0) d_q[gw] = sum + Qb[l*AT + a];
}

// ------------------------- scores from bf16 kproj -------------------------
// grid (LTD/64, BB), 256 threads. warp w handles 8 lt rows. q/Vw held in regs.
__global__ void __launch_bounds__(256) k_scores(const float* __restrict__ Vw, const float* __restrict__ Vb){
    int b = blockIdx.y;
    int lt0 = blockIdx.x*64;
    int l = lt0 >> 9;
    int w = threadIdx.x >> 5, lane = threadIdx.x & 31;

    float q8[8], v8[8];
    if (lane < 25){
        const float4* qp = reinterpret_cast<const float4*>(d_q + (size_t)(l*BB + b)*AT + lane*8);
        const float4* vp = reinterpret_cast<const float4*>(Vw + l*AT + lane*8);
        float4 a = qp[0], c = qp[1], e = vp[0], f = vp[1];
        q8[0]=a.x;q8[1]=a.y;q8[2]=a.z;q8[3]=a.w;q8[4]=c.x;q8[5]=c.y;q8[6]=c.z;q8[7]=c.w;
        v8[0]=e.x;v8[1]=e.y;v8[2]=e.z;v8[3]=e.w;v8[4]=f.x;v8[5]=f.y;v8[6]=f.z;v8[7]=f.w;
    } else {
        #pragma unroll
        for (int i=0;i<8;i++){ q8[i]=0.f; v8[i]=0.f; }
    }
    float vb = Vb[l];

    const uint4* kp = reinterpret_cast<const uint4*>(d_kprojh);
    int lt = lt0 + w*8;
    size_t row = ((size_t)lt*BB + b)*25;   // uint4 units per row = 200*2/16 = 25
    uint4 cur = make_uint4(0,0,0,0);
    if (lane < 25) cur = kp[row + lane];

    #pragma unroll
    for (int r=0;r<8;r++){
        uint4 nxt = make_uint4(0,0,0,0);
        if (r < 7 && lane < 25) nxt = kp[row + (size_t)(r+1)*BB*25 + lane];
        const __nv_bfloat162* p = reinterpret_cast<const __nv_bfloat162*>(&cur);
        float sum = 0.f;
        #pragma unroll
        for (int j=0;j<4;j++){
            float2 f2 = __bfloat1622float2(p[j]);
            sum = fmaf(v8[2*j+0], tanh_fast(f2.x + q8[2*j+0]), sum);
            sum = fmaf(v8[2*j+1], tanh_fast(f2.y + q8[2*j+1]), sum);
        }
        #pragma unroll
        for (int off=16; off; off>>=1) sum += __shfl_xor_sync(0xffffffffu, sum, off);
        if (lane == 0) d_scores[(size_t)b*LTD + lt + r] = sum + vb;
        cur = nxt;
    }
}

// ------------------------- fused softmax + partial context (bf16 enc) -------------------------
// grid (BB, 4), 256 threads. block computes softmax weights (redundant x4), then
// accumulates its 256-lt chunk of the context into d_ctxp[split].
__global__ void __launch_bounds__(256) k_ctx(){
    __shared__ float sw[LTD];
    __shared__ float red[256];
    int b = blockIdx.x, c = blockIdx.y, tid = threadIdx.x;

    float4 s4 = *reinterpret_cast<const float4*>(d_scores + (size_t)b*LTD + tid*4);
    float mx = fmaxf(fmaxf(s4.x, s4.y), fmaxf(s4.z, s4.w));
    red[tid] = mx; __syncthreads();
    for (int st=128; st>0; st>>=1){ if (tid<st) red[tid]=fmaxf(red[tid],red[tid+st]); __syncthreads(); }
    float m = red[0]; __syncthreads();
    float e0 = __expf(s4.x-m), e1 = __expf(s4.y-m), e2 = __expf(s4.z-m), e3 = __expf(s4.w-m);
    sw[tid*4+0]=e0; sw[tid*4+1]=e1; sw[tid*4+2]=e2; sw[tid*4+3]=e3;
    red[tid] = e0+e1+e2+e3; __syncthreads();
    for (int st=128; st>0; st>>=1){ if (tid<st) red[tid]+=red[tid+st]; __syncthreads(); }
    float inv = 1.0f/red[0]; __syncthreads();
    sw[c*256 + tid] *= inv;            // rescale only this block's chunk
    __syncthreads();

    // accumulate 256 lt x 512 h (bf16), thread owns h = 2*tid, 2*tid+1
    const __nv_bfloat162* ep = reinterpret_cast<const __nv_bfloat162*>(d_ench) +
                               ((size_t)b*LTD + c*256)*(HH/2) + tid;
    const float* wc = &sw[c*256];
    float ax = 0.f, ay = 0.f;
    #pragma unroll 16
    for (int j=0;j<256;j++){
        float wj = wc[j];
        float2 f2 = __bfloat1622float2(ep[(size_t)j*(HH/2)]);
        ax = fmaf(wj, f2.x, ax);
        ay = fmaf(wj, f2.y, ay);
    }
    float2* outp = reinterpret_cast<float2*>(d_ctxp + (size_t)c*BB*HH + (size_t)b*HH) + tid;
    *outp = make_float2(ax, ay);
}

// ------------------------- per-step GRU matmuls (gi & gh in one launch) -------------------------
__global__ void __launch_bounds__(256) k_grumm(
    int layer, int s, int cur,
    const float* __restrict__ Wih0, const float* __restrict__ Whh0, const float* __restrict__ bhh0,
    const float* __restrict__ Wih1, const float* __restrict__ bih1,
    const float* __restrict__ Whh1, const float* __restrict__ bhh1)
{
    const float* Aa = nullptr; const float* Bw; int ldb;
    const float* add = nullptr; const float* bias = nullptr; float* C;
    bool merge = false;
    if (layer == 0){
        if (blockIdx.y == 0){ merge = true;      Bw = Wih0 + EE; ldb = EE + HH; add = d_giEmb + (size_t)s*BB*3*HH; C = d_gi0; }
        else                { Aa = d_h0[cur];    Bw = Whh0;      ldb = HH;      bias = bhh0;                        C = d_gh0; }
    } else {
        if (blockIdx.y == 0){ Aa = d_h0[cur^1];  Bw = Wih1;      ldb = HH;      bias = bih1;                        C = d_gi1; }
        else                { Aa = d_h1[cur];    Bw = Whh1;      ldb = HH;      bias = bhh1;                        C = d_gh1; }
    }
    __shared__ float As[16][68];
    __shared__ float Bs[16][20];
    int tid = threadIdx.x;
    int n0 = blockIdx.x*16;
    int ty = tid >> 4, tx = tid & 15;
    int tm0 = ty*4;
    int arow = tid >> 2, akc = (tid & 3) << 2;
    float acc0=0.f, acc1=0.f, acc2=0.f, acc3=0.f;

    for (int k0=0; k0<HH; k0+=16){
        float4 av;
        if (merge){
            const float* p = d_ctxp + (size_t)arow*HH + k0 + akc;
            float4 a0 = *reinterpret_cast<const float4*>(p);
            float4 a1 = *reinterpret_cast<const float4*>(p + BB*HH);
            float4 a2 = *reinterpret_cast<const float4*>(p + 2*BB*HH);
            float4 a3 = *reinterpret_cast<const float4*>(p + 3*BB*HH);
            av.x = a0.x+a1.x+a2.x+a3.x; av.y = a0.y+a1.y+a2.y+a3.y;
            av.z = a0.z+a1.z+a2.z+a3.z; av.w = a0.w+a1.w+a2.w+a3.w;
        } else {
            av = *reinterpret_cast<const float4*>(Aa + (size_t)arow*HH + k0 + akc);
        }
        As[akc+0][arow]=av.x; As[akc+1][arow]=av.y; As[akc+2][arow]=av.z; As[akc+3][arow]=av.w;
        if (tid < 64){
            float4 bv = *reinterpret_cast<const float4*>(Bw + (size_t)(n0 + arow)*ldb + k0 + akc);
            Bs[akc+0][arow]=bv.x; Bs[akc+1][arow]=bv.y; Bs[akc+2][arow]=bv.z; Bs[akc+3][arow]=bv.w;
        }
        __syncthreads();
        #pragma unroll
        for (int kk=0; kk<16; kk++){
            float4 a = *reinterpret_cast<const float4*>(&As[kk][tm0]);
            float bv = Bs[kk][tx];
            acc0 = fmaf(a.x, bv, acc0);
            acc1 = fmaf(a.y, bv, acc1);
            acc2 = fmaf(a.z, bv, acc2);
            acc3 = fmaf(a.w, bv, acc3);
        }
        __syncthreads();
    }
    int n = n0 + tx;
    float base = bias ? bias[n] : 0.f;
    float r[4] = {acc0+base, acc1+base, acc2+base, acc3+base};
    #pragma unroll
    for (int i=0;i<4;i++){
        size_t off = (size_t)(tm0+i)*(3*HH) + n;
        float v = r[i];
        if (add) v += add[off];
        C[off] = v;
    }
}

// ------------------------- GRU gates -------------------------
__global__ void k_gates0(int cur){
    int idx = blockIdx.x*256 + threadIdx.x;       // BB*HH
    int b = idx >> 9, j = idx & 511;
    const float* gi = d_gi0 + (size_t)b*3*HH;
    const float* gh = d_gh0 + (size_t)b*3*HH;
    float r = sigm(gi[j] + gh[j]);
    float z = sigm(gi[j+HH] + gh[j+HH]);
    float n = tanhf(gi[j+2*HH] + r*gh[j+2*HH]);
    d_h0[cur^1][idx] = (1.0f - z)*n + z*d_h0[cur][idx];
}
__global__ void k_gates1(int cur, int s){
    int idx = blockIdx.x*256 + threadIdx.x;
    int b = idx >> 9, j = idx & 511;
    const float* gi = d_gi1 + (size_t)b*3*HH;
    const float* gh = d_gh1 + (size_t)b*3*HH;
    float r = sigm(gi[j] + gh[j]);
    float z = sigm(gi[j+HH] + gh[j+HH]);
    float n = tanhf(gi[j+2*HH] + r*gh[j+2*HH]);
    float hv = (1.0f - z)*n + z*d_h1[cur][idx];
    d_h1[cur^1][idx] = hv;
    d_hstates[(size_t)s*BB*HH + idx] = hv;
}

// ------------------------- launch -------------------------
extern "C" void kernel_launch(void* const* d_in, const int* in_sizes, int n_in,
                              void* d_out, int out_size){
    const float* enc = (const float*)d_in[0];
    const float* efs = (const float*)d_in[1];
    const int*   tgt = (const int*)  d_in[2];
    const float* Qw  = (const float*)d_in[3];
    const float* Qb  = (const float*)d_in[4];
    const float* Kw  = (const float*)d_in[5];
    const float* Kb  = (const float*)d_in[6];
    const float* Vw  = (const float*)d_in[7];
    const float* Vb  = (const float*)d_in[8];
    const float* emb = (const float*)d_in[9];
    const float* Wih0= (const float*)d_in[10];
    const float* Whh0= (const float*)d_in[11];
    const float* bih0= (const float*)d_in[12];
    const float* bhh0= (const float*)d_in[13];
    const float* Wih1= (const float*)d_in[14];
    const float* Whh1= (const float*)d_in[15];
    const float* bih1= (const float*)d_in[16];
    const float* bhh1= (const float*)d_in[17];
    const float* Pw  = (const float*)d_in[18];
    const float* Pb  = (const float*)d_in[19];
    float* out = (float*)d_out;

    float *p_xemb, *p_giEmb, *p_kproj, *p_hstates;
    cudaGetSymbolAddress((void**)&p_xemb,    d_xemb);
    cudaGetSymbolAddress((void**)&p_giEmb,   d_giEmb);
    cudaGetSymbolAddress((void**)&p_kproj,   d_kproj);
    cudaGetSymbolAddress((void**)&p_hstates, d_hstates);

    // one-time precomputation
    k_init<<<(BB*HH + 255)/256, 256>>>(efs);
    k_embed<<<SS*BB, 128>>>(tgt, emb);
    k_enc2bf<<<LTD, 256>>>(enc);
    {   // gi_emb[s,b,:] = relu(emb) @ Wih0[:, :EE]^T + bih0
        dim3 g(SS*BB/128, (3*HH)/64, 1);
        k_sgemm<false><<<g, 256>>>(p_xemb, EE, 0, Wih0, EE+HH, 0, bih0, 0,
                                   p_giEmb, 3*HH, 0, SS*BB, 3*HH, EE);
    }
    {   // kproj[l,t,b,:] = enc @ Kw[l]^T + Kb[l]
        dim3 g(TT*BB/128, (AT+63)/64, LL);
        k_sgemm<false><<<g, 256>>>(enc, HH, (long long)TT*BB*HH,
                                   Kw, HH, (long long)AT*HH,
                                   Kb, AT,
                                   p_kproj, AT, (long long)TT*BB*AT,
                                   TT*BB, AT, HH);
    }
    k_kproj2bf<<<6400, 256>>>();

    // sequential decode loop
    for (int s = 0; s < SS; s++){
        int cur = s & 1;
        k_q<<<(LL*BB*AT)/8, 256>>>(Qw, Qb, cur);
        { dim3 gs(LTD/64, BB); k_scores<<<gs, 256>>>(Vw, Vb); }
        { dim3 gc(BB, 4); k_ctx<<<gc, 256>>>(); }
        { dim3 gm(3*HH/16, 2);
          k_grumm<<<gm, 256>>>(0, s, cur, Wih0, Whh0, bhh0, Wih1, bih1, Whh1, bhh1);
          k_gates0<<<BB*HH/256, 256>>>(cur);
          k_grumm<<<gm, 256>>>(1, s, cur, Wih0, Whh0, bhh0, Wih1, bih1, Whh1, bhh1);
          k_gates1<<<BB*HH/256, 256>>>(cur, s);
        }
    }

    {   // deferred output projection: logits = hstates @ Pw^T + Pb, permuted to (B,S,V)
        dim3 g(SS*BB/128, (VV+63)/64, 1);
        k_sgemm<true><<<g, 256>>>(p_hstates, HH, 0, Pw, HH, 0, Pb, 0,
                                  out, VV, 0, SS*BB, VV, HH);
    }
}